// round 12
// baseline (speedup 1.0000x reference)
#include <cuda_runtime.h>
#include <cuda_fp16.h>
#include <cstdint>
#include <cstddef>

#define BATCH   16
#define LSEQ    4096
#define INDIM   64
#define DMODEL  128
#define OUTDIM  64
#define TCHUNK  128
#define NCHUNK  32          // LSEQ / TCHUNK
#define CHAINS  256         // 128 p * {re,im}

// ---------------- device scratch (no allocations allowed) ----------------
__device__ __half g_w[(size_t)BATCH * LSEQ * CHAINS];        // local-scan w (fp16, 33.5MB)
__device__ float2 g_carry[BATCH * NCHUNK * CHAINS];          // chunk-local final states
__device__ __half g_BWh[CHAINS * INDIM];                     // fused B_part * W_in (fp16, [k][i])
__device__ float  g_BuC[CHAINS];                             // B_part * b_in
__device__ float4 g_Pm[TCHUNK * DMODEL];                     // M^{j+1} per p (kD prefix uses row 127)
__device__ float2 g_Pzw[TCHUNK * DMODEL];                    // (M^{j+1}).{21,22} per (j,p)  [kD fixup]
__device__ __half g_WcF[OUTDIM * 320];                       // fused output matrix fp16, [o][k]
__device__ float  g_bias[OUTDIM];

// ---------------- helpers ----------------
__device__ __forceinline__ uint32_t smem_u32(const void* p) {
    uint32_t a;
    asm("{ .reg .u64 t; cvta.to.shared.u64 t, %1; cvt.u32.u64 %0, t; }" : "=r"(a) : "l"(p));
    return a;
}
__device__ __forceinline__ void ldsm_x4(uint32_t &r0, uint32_t &r1, uint32_t &r2, uint32_t &r3, uint32_t addr) {
    asm volatile("ldmatrix.sync.aligned.m8n8.x4.shared.b16 {%0,%1,%2,%3}, [%4];"
                 : "=r"(r0), "=r"(r1), "=r"(r2), "=r"(r3) : "r"(addr));
}
__device__ __forceinline__ void mma16816(float &c0, float &c1, float &c2, float &c3,
                                         uint32_t a0, uint32_t a1, uint32_t a2, uint32_t a3,
                                         uint32_t b0, uint32_t b1) {
    asm volatile("mma.sync.aligned.m16n8k16.row.col.f32.f16.f16.f32 "
                 "{%0,%1,%2,%3}, {%4,%5,%6,%7}, {%8,%9}, {%0,%1,%2,%3};"
                 : "+f"(c0), "+f"(c1), "+f"(c2), "+f"(c3)
                 : "r"(a0), "r"(a1), "r"(a2), "r"(a3), "r"(b0), "r"(b1));
}
__device__ __forceinline__ void cp_async16(uint32_t smem_dst, const void* gsrc) {
    asm volatile("cp.async.cg.shared.global [%0], [%1], 16;" :: "r"(smem_dst), "l"(gsrc) : "memory");
}
__device__ __forceinline__ void cp_async_commit() {
    asm volatile("cp.async.commit_group;" ::: "memory");
}
__device__ __forceinline__ void cp_async_wait0() {
    asm volatile("cp.async.wait_group 0;" ::: "memory");
}

// implicit-LinOSS per-p recurrence coefficients
__device__ __forceinline__ void lin_coefs(const float* __restrict__ A_diag,
                                          const float* __restrict__ steps, int p,
                                          float& m11, float& m12, float& m21, float& m22,
                                          float& f1, float& f2) {
    float A  = fmaxf(A_diag[p], 0.0f);
    float dt = 1.0f / (1.0f + expf(-steps[p]));
    float dt2A = dt * dt * A;
    float S  = 1.0f / (1.0f + dt2A);
    m11 = 1.0f - dt2A * S;
    m12 = -dt * A * S;
    m21 = dt * S;
    m22 = S;
    f1  = m11 * dt;
    f2  = m21 * dt;
}

// ================= kernel A: build fused matrices + power tables =================
__global__ __launch_bounds__(256) void kA(const float* __restrict__ W_in,
                                          const float* __restrict__ b_in,
                                          const float* __restrict__ A_diag,
                                          const float* __restrict__ Bmat,
                                          const float* __restrict__ Cmat,
                                          const float* __restrict__ Dvec,
                                          const float* __restrict__ steps,
                                          const float* __restrict__ W_out,
                                          const float* __restrict__ b_out) {
    __shared__ float sbuf[11264];
    const int bid = blockIdx.x, tid = threadIdx.x;

    if (bid < 16) {
        float* Wins = sbuf;                   // [128][64]
        float* Bs   = sbuf + DMODEL * INDIM;  // [16][128]
        for (int i = tid; i < DMODEL * INDIM; i += 256) Wins[i] = W_in[i];
        const int k0 = bid * 16;
        for (int i = tid; i < 16 * DMODEL; i += 256) {
            int kk = i >> 7, h = i & 127;
            int k = k0 + kk, p = k & 127, part = k >> 7;
            Bs[i] = Bmat[(p * DMODEL + h) * 2 + part];
        }
        __syncthreads();
        for (int e = tid; e < 16 * INDIM; e += 256) {
            int kk = e >> 6, i = e & 63;
            float acc = 0.0f;
            #pragma unroll 8
            for (int h = 0; h < DMODEL; h++) acc = fmaf(Bs[kk * DMODEL + h], Wins[h * INDIM + i], acc);
            g_BWh[(k0 + kk) * INDIM + i] = __float2half(acc);
        }
        if (bid == 0) {
            int k = tid, p = k & 127, part = k >> 7;
            float s = 0.0f;
            for (int h = 0; h < DMODEL; h++) s = fmaf(Bmat[(p * DMODEL + h) * 2 + part], b_in[h], s);
            g_BuC[k] = s;
        }
    } else if (bid < 32) {
        float* Wos = sbuf;                    // [64][129] padded
        float* Cs  = sbuf + OUTDIM * 129;     // [20][128]
        for (int i = tid; i < OUTDIM * DMODEL; i += 256) {
            int o = i >> 7, h = i & 127;
            Wos[o * 129 + h] = W_out[i];
        }
        const int kb0 = (bid - 16) * 20;
        for (int i = tid; i < 20 * DMODEL; i += 256) {
            int kk = i >> 7, h = i & 127;
            int k = kb0 + kk;
            float v;
            if (k < 128)      v =  Cmat[(h * DMODEL + k) * 2 + 0];
            else if (k < 256) v = -Cmat[(h * DMODEL + (k - 128)) * 2 + 1];
            else              v =  Dvec[h] * W_in[h * INDIM + (k - 256)];
            Cs[i] = v;
        }
        __syncthreads();
        for (int e = tid; e < 20 * OUTDIM; e += 256) {
            int kk = e >> 6, o = e & 63;
            float acc = 0.0f;
            #pragma unroll 8
            for (int h = 0; h < DMODEL; h++) acc = fmaf(Cs[kk * DMODEL + h], Wos[o * 129 + h], acc);
            g_WcF[o * 320 + (kb0 + kk)] = __float2half(acc);
        }
        if (bid == 16 && tid < OUTDIM) {
            float s = b_out[tid];
            for (int h = 0; h < DMODEL; h++) s = fmaf(W_out[tid * DMODEL + h] * Dvec[h], b_in[h], s);
            g_bias[tid] = s;
        }
    } else {
        if (tid < DMODEL) {
            float m11, m12, m21, m22, f1, f2;
            lin_coefs(A_diag, steps, tid, m11, m12, m21, m22, f1, f2);
            float c11 = m11, c12 = m12, c21 = m21, c22 = m22;
            for (int j = 0; j < TCHUNK; j++) {
                g_Pm[j * DMODEL + tid]  = make_float4(c11, c12, c21, c22);
                g_Pzw[j * DMODEL + tid] = make_float2(c21, c22);
                float n11 = m11 * c11 + m12 * c21;
                float n12 = m11 * c12 + m12 * c22;
                float n21 = m21 * c11 + m22 * c21;
                float n22 = m21 * c12 + m22 * c22;
                c11 = n11; c12 = n12; c21 = n21; c22 = n22;
            }
        }
    }
}

// ================= kernel B: tensor-core Bu GEMM (16 warps) + fused scan =================
// 512 threads. GEMM1 n-split: warps 0-7 cols 0-127, warps 8-15 cols 128-255.
// Dynamic smem: xh [128][72] f16 | BWh [256][72] f16 | Bus [128][264] f32
#define KB_XH    0
#define KB_BWH   18432
#define KB_BUS   55296
#define KB_SMEM  190464
#define APAD 72
#define BUSP 264
__global__ __launch_bounds__(512) void kB(const float* __restrict__ x,
                                          const float* __restrict__ A_diag,
                                          const float* __restrict__ steps) {
    extern __shared__ char dsm[];
    __half* xh  = (__half*)(dsm + KB_XH);
    __half* bwh = (__half*)(dsm + KB_BWH);
    float*  bus = (float*)(dsm + KB_BUS);

    const int b = blockIdx.x >> 5, c = blockIdx.x & 31;
    const int R0 = b * LSEQ + c * TCHUNK;
    const int tid = threadIdx.x;
    const int wid = tid >> 5, lane = tid & 31;

    // ---- stage x tile -> fp16 [128][72] ----
    {
        const float4* xg = (const float4*)(x + (size_t)R0 * INDIM);
        #pragma unroll
        for (int it = 0; it < 4; it++) {
            int idx = tid + it * 512;            // float4 index, 2048 total
            int r = idx >> 4, c4 = idx & 15;
            float4 v = xg[idx];
            __half2 h0 = __floats2half2_rn(v.x, v.y);
            __half2 h1 = __floats2half2_rn(v.z, v.w);
            *(uint2*)(xh + r * APAD + c4 * 4) =
                make_uint2(*(uint32_t*)&h0, *(uint32_t*)&h1);
        }
    }
    // ---- stage BW -> [256][72] ----
    {
        const uint4* bg = (const uint4*)g_BWh;   // 8 halves per uint4, 2048 total
        #pragma unroll
        for (int it = 0; it < 4; it++) {
            int idx = tid + it * 512;
            int r = idx >> 3, seg = idx & 7;
            *(uint4*)(bwh + r * APAD + seg * 8) = bg[idx];
        }
    }
    __syncthreads();

    // ---- GEMM1: warp (wq, wg): rows 16*wq..+15, cols wg*128..+127 ----
    {
        const uint32_t sX = smem_u32(xh), sW = smem_u32(bwh);
        const int wq = wid & 7, wg = wid >> 3;
        const int q = lane >> 3, rr = lane & 7;
        const uint32_t aBase = sX + (uint32_t)(((wq * 16 + (q & 1) * 8 + rr) * APAD + (q >> 1) * 8) * 2);
        const uint32_t bBase0 = sW + (uint32_t)(((wg * 128 + (q >> 1) * 8 + rr) * APAD + (q & 1) * 8) * 2);

        float acc[16][4];
        #pragma unroll
        for (int nt = 0; nt < 16; nt++) {
            acc[nt][0] = 0.f; acc[nt][1] = 0.f; acc[nt][2] = 0.f; acc[nt][3] = 0.f;
        }
        #pragma unroll
        for (int k16 = 0; k16 < 4; k16++) {
            uint32_t a0, a1, a2, a3;
            ldsm_x4(a0, a1, a2, a3, aBase + (uint32_t)(k16 * 32));
            #pragma unroll
            for (int ntp = 0; ntp < 8; ntp++) {
                uint32_t b0, b1, b2, b3;
                ldsm_x4(b0, b1, b2, b3, bBase0 + (uint32_t)(ntp * 16 * APAD * 2 + k16 * 32));
                mma16816(acc[ntp * 2][0], acc[ntp * 2][1], acc[ntp * 2][2], acc[ntp * 2][3],
                         a0, a1, a2, a3, b0, b1);
                mma16816(acc[ntp * 2 + 1][0], acc[ntp * 2 + 1][1], acc[ntp * 2 + 1][2], acc[ntp * 2 + 1][3],
                         a0, a1, a2, a3, b2, b3);
            }
        }
        // fragments -> Bus
        const int g = lane >> 2, ci = lane & 3;
        const int row0 = wq * 16 + g;
        #pragma unroll
        for (int nt = 0; nt < 16; nt++) {
            int col = wg * 128 + nt * 8 + ci * 2;
            *(float2*)(bus + row0 * BUSP + col)       = make_float2(acc[nt][0], acc[nt][1]);
            *(float2*)(bus + (row0 + 8) * BUSP + col) = make_float2(acc[nt][2], acc[nt][3]);
        }
    }
    __syncthreads();

    // ---- fused chunk-local scan: threads 0-255, chain k = tid ----
    if (tid < CHAINS) {
        const int k = tid, p = k & 127;
        float m11, m12, m21, m22, f1, f2;
        lin_coefs(A_diag, steps, p, m11, m12, m21, m22, f1, f2);
        const float buc = g_BuC[k];
        float z = 0.0f, w = 0.0f;
        __half* wout = g_w + (size_t)R0 * CHAINS + k;
        const float* bcol = bus + k;
        for (int t = 0; t < TCHUNK; t += 4) {
            float bu[4];
            #pragma unroll
            for (int j = 0; j < 4; j++) bu[j] = bcol[(t + j) * BUSP] + buc;
            #pragma unroll
            for (int j = 0; j < 4; j++) {
                float nz = fmaf(m11, z, fmaf(m12, w, f1 * bu[j]));
                float nw = fmaf(m21, z, fmaf(m22, w, f2 * bu[j]));
                z = nz; w = nw;
                wout[(size_t)(t + j) * CHAINS] = __float2half(w);
            }
        }
        g_carry[(b * NCHUNK + c) * CHAINS + k] = make_float2(z, w);
    }
}

// ================= kernel D: prefix (ex-kC) + carry fixup + output GEMM (pipelined) =================
// Dynamic smem: smA [128][72] f16 | smB [64][72] f16 | xraw [128][68] f32 | czs/cws [256] f32
#define XRP 68   // xraw row stride in floats (272B, 16B-aligned)
#define KD_SMA   0
#define KD_SMB   18432
#define KD_XRAW  27648
#define KD_CZS   62464
#define KD_CWS   63488
#define KD_SMEM  64512
__global__ __launch_bounds__(256) void kD(const float* __restrict__ x,
                                          float* __restrict__ out) {
    extern __shared__ char dsmD[];
    __half* smA  = (__half*)(dsmD + KD_SMA);
    __half* smB  = (__half*)(dsmD + KD_SMB);
    float*  xraw = (float*)(dsmD + KD_XRAW);
    float*  czs  = (float*)(dsmD + KD_CZS);
    float*  cws  = (float*)(dsmD + KD_CWS);

    const int R0 = blockIdx.x * 128;          // global row = b*LSEQ + t0
    const int b  = R0 >> 12;
    const int cc = (R0 & 4095) >> 7;          // chunk index
    const int tid = threadIdx.x;
    const int wid = tid >> 5, lane = tid & 31;

    const uint32_t sA = smem_u32(smA);
    const uint32_t sB = smem_u32(smB);
    const uint32_t sXr = smem_u32(xraw);

    // ---- issue cp.async for x tile (hidden behind slices 0-3) ----
    {
        const float* xg = x + (size_t)R0 * INDIM;
        #pragma unroll
        for (int it = 0; it < 8; it++) {
            int idx = tid + it * 256;            // 16B chunk index, 2048 total
            int r = idx >> 4, seg = idx & 15;
            cp_async16(sXr + (uint32_t)((r * XRP + seg * 4) * 4), xg + idx * 4);
        }
        cp_async_commit();
    }

    const int kp = lane;            // k-pair within slice (k = 2kp, 2kp+1)
    const int rq = wid;             // 16-row segment
    const int brow = tid >> 2, bseg = tid & 3;   // B: row o, 16-half segment

    // ---- initial prefetch: w slice 0 + B slice 0 ----
    uint32_t wbuf[16];
    uint4 bb0, bb1;
    {
        const __half* wsrc = g_w + (size_t)R0 * CHAINS + 2 * kp;
        #pragma unroll
        for (int j = 0; j < 16; j++)
            wbuf[j] = *(const uint32_t*)(wsrc + (size_t)(rq * 16 + j) * CHAINS);
        const uint4* bsrc = (const uint4*)(g_WcF + brow * 320 + bseg * 16);
        bb0 = bsrc[0]; bb1 = bsrc[1];
    }

    // ---- prefix over carries (replaces kC): chain k = tid ----
    {
        const int p = tid & 127;
        float4 mt = g_Pm[(TCHUNK - 1) * DMODEL + p];    // M^128
        float z = 0.0f, w = 0.0f;
        int c = 0;
        while (c + 8 <= cc) {
            float2 lc[8];
            #pragma unroll
            for (int j = 0; j < 8; j++)
                lc[j] = g_carry[(b * NCHUNK + c + j) * CHAINS + tid];
            #pragma unroll
            for (int j = 0; j < 8; j++) {
                float nz = fmaf(mt.x, z, fmaf(mt.y, w, lc[j].x));
                float nw = fmaf(mt.z, z, fmaf(mt.w, w, lc[j].y));
                z = nz; w = nw;
            }
            c += 8;
        }
        for (; c < cc; c++) {
            float2 lc = g_carry[(b * NCHUNK + c) * CHAINS + tid];
            float nz = fmaf(mt.x, z, fmaf(mt.y, w, lc.x));
            float nw = fmaf(mt.z, z, fmaf(mt.w, w, lc.y));
            z = nz; w = nw;
        }
        czs[tid] = z; cws[tid] = w;
    }
    __syncthreads();

    // ldmatrix lane-address components
    const int q  = lane >> 3, rr = lane & 7;
    const uint32_t aBase = sA + (uint32_t)(((wid * 16 + (q & 1) * 8 + rr) * APAD + (q >> 1) * 8) * 2);
    uint32_t bBase[4];
    #pragma unroll
    for (int ntp = 0; ntp < 4; ntp++)
        bBase[ntp] = sB + (uint32_t)(((ntp * 16 + (q >> 1) * 8 + rr) * APAD + (q & 1) * 8) * 2);

    float acc[8][4];
    #pragma unroll
    for (int nt = 0; nt < 8; nt++)
        #pragma unroll
        for (int i = 0; i < 4; i++) acc[nt][i] = 0.0f;

    for (int s = 0; s < 5; s++) {
        if (s == 4) { cp_async_wait0(); __syncthreads(); }

        // ---- stage B slice from prefetched regs ----
        {
            uint4* dst = (uint4*)(smB + brow * APAD + bseg * 16);
            dst[0] = bb0; dst[1] = bb1;
        }
        // ---- stage A slice: fixup (s<4) or x passthrough (s==4) ----
        if (s < 4) {
            const int k2 = kp * 2;
            const int kg = s * 64 + k2;
            const int p0 = kg & 127;
            const float cz0 = czs[kg],     cw0 = cws[kg];
            const float cz1 = czs[kg + 1], cw1 = cws[kg + 1];
            #pragma unroll
            for (int j = 0; j < 16; j++) {
                int r = rq * 16 + j;
                float4 pz = *(const float4*)(&g_Pzw[r * DMODEL + p0]);  // {z0,w0,z1,w1}
                __half2 wh = *(const __half2*)(&wbuf[j]);
                float2 wf = __half22float2(wh);
                float v0 = fmaf(pz.x, cz0, fmaf(pz.y, cw0, wf.x));
                float v1 = fmaf(pz.z, cz1, fmaf(pz.w, cw1, wf.y));
                *(__half2*)(smA + r * APAD + k2) = __floats2half2_rn(v0, v1);
            }
        } else {
            const int k2 = kp * 2;
            #pragma unroll
            for (int j = 0; j < 16; j++) {
                int r = rq * 16 + j;
                float2 xv = *(const float2*)(xraw + r * XRP + k2);
                *(__half2*)(smA + r * APAD + k2) = __floats2half2_rn(xv.x, xv.y);
            }
        }
        __syncthreads();

        // ---- prefetch next slice (overlaps MMA below) ----
        if (s < 3) {
            const __half* wsrc = g_w + (size_t)R0 * CHAINS + (s + 1) * 64 + 2 * kp;
            #pragma unroll
            for (int j = 0; j < 16; j++)
                wbuf[j] = *(const uint32_t*)(wsrc + (size_t)(rq * 16 + j) * CHAINS);
        }
        if (s < 4) {
            const uint4* bsrc = (const uint4*)(g_WcF + brow * 320 + (s + 1) * 64 + bseg * 16);
            bb0 = bsrc[0]; bb1 = bsrc[1];
        }

        // ---- compute: 4 k16 steps ----
        #pragma unroll
        for (int k16 = 0; k16 < 4; k16++) {
            const uint32_t kofs = (uint32_t)(k16 * 16 * 2);
            uint32_t a0, a1, a2, a3;
            ldsm_x4(a0, a1, a2, a3, aBase + kofs);
            uint32_t bf[4][4];
            #pragma unroll
            for (int ntp = 0; ntp < 4; ntp++)
                ldsm_x4(bf[ntp][0], bf[ntp][1], bf[ntp][2], bf[ntp][3], bBase[ntp] + kofs);
            #pragma unroll
            for (int ntp = 0; ntp < 4; ntp++) {
                mma16816(acc[ntp * 2][0], acc[ntp * 2][1], acc[ntp * 2][2], acc[ntp * 2][3],
                         a0, a1, a2, a3, bf[ntp][0], bf[ntp][1]);
                mma16816(acc[ntp * 2 + 1][0], acc[ntp * 2 + 1][1], acc[ntp * 2 + 1][2], acc[ntp * 2 + 1][3],
                         a0, a1, a2, a3, bf[ntp][2], bf[ntp][3]);
            }
        }
        __syncthreads();
    }

    // ---- epilogue: add bias, store directly from fragments ----
    const int g = lane >> 2, cpair = (lane & 3) * 2;
    const int row0 = R0 + wid * 16 + g;
    float* og0 = out + (size_t)row0 * OUTDIM;
    float* og1 = og0 + 8 * OUTDIM;
    #pragma unroll
    for (int nt = 0; nt < 8; nt++) {
        int col = nt * 8 + cpair;
        float b0 = g_bias[col], b1 = g_bias[col + 1];
        *(float2*)(og0 + col) = make_float2(acc[nt][0] + b0, acc[nt][1] + b1);
        *(float2*)(og1 + col) = make_float2(acc[nt][2] + b0, acc[nt][3] + b1);
    }
}

extern "C" void kernel_launch(void* const* d_in, const int* in_sizes, int n_in,
                              void* d_out, int out_size) {
    const float* x      = (const float*)d_in[0];
    const float* W_in   = (const float*)d_in[1];
    const float* b_in   = (const float*)d_in[2];
    const float* A_diag = (const float*)d_in[3];
    const float* Bmat   = (const float*)d_in[4];
    const float* Cmat   = (const float*)d_in[5];
    const float* Dvec   = (const float*)d_in[6];
    const float* steps  = (const float*)d_in[7];
    const float* W_out  = (const float*)d_in[8];
    const float* b_out  = (const float*)d_in[9];
    float* out = (float*)d_out;

    cudaFuncSetAttribute(kB, cudaFuncAttributeMaxDynamicSharedMemorySize, KB_SMEM);
    cudaFuncSetAttribute(kD, cudaFuncAttributeMaxDynamicSharedMemorySize, KD_SMEM);

    kA<<<33, 256>>>(W_in, b_in, A_diag, Bmat, Cmat, Dvec, steps, W_out, b_out);
    kB<<<BATCH * NCHUNK, 512, KB_SMEM>>>(x, A_diag, steps);
    kD<<<(BATCH * LSEQ) / TCHUNK, 256, KD_SMEM>>>(x, out);
}

// round 13
// speedup vs baseline: 1.2934x; 1.2934x over previous
#include <cuda_runtime.h>
#include <cuda_fp16.h>
#include <cstdint>
#include <cstddef>

#define BATCH   16
#define LSEQ    4096
#define INDIM   64
#define DMODEL  128
#define OUTDIM  64
#define TCHUNK  128
#define NCHUNK  32          // LSEQ / TCHUNK
#define CHAINS  256         // 128 p * {re,im}

// ---------------- device scratch (no allocations allowed) ----------------
__device__ __half g_w[(size_t)BATCH * LSEQ * CHAINS];        // local-scan w (fp16, 33.5MB)
__device__ float2 g_carry[BATCH * NCHUNK * CHAINS];          // chunk-local final states
__device__ float2 g_cin[BATCH * NCHUNK * CHAINS];            // exclusive cross-chunk prefix
__device__ __half g_BWh[CHAINS * INDIM];                     // fused B_part * W_in (fp16, [k][i])
__device__ float  g_BuC[CHAINS];                             // B_part * b_in
__device__ float4 g_Pm[TCHUNK * DMODEL];                     // M^{j+1} per p (kC uses row 127)
__device__ float2 g_Pzw[TCHUNK * DMODEL];                    // (M^{j+1}).{21,22} per (j,p)  [kD fixup]
__device__ __half g_WcF[OUTDIM * 320];                       // fused output matrix fp16, [o][k]
__device__ float  g_bias[OUTDIM];

// ---------------- helpers ----------------
__device__ __forceinline__ uint32_t smem_u32(const void* p) {
    uint32_t a;
    asm("{ .reg .u64 t; cvta.to.shared.u64 t, %1; cvt.u32.u64 %0, t; }" : "=r"(a) : "l"(p));
    return a;
}
__device__ __forceinline__ void ldsm_x4(uint32_t &r0, uint32_t &r1, uint32_t &r2, uint32_t &r3, uint32_t addr) {
    asm volatile("ldmatrix.sync.aligned.m8n8.x4.shared.b16 {%0,%1,%2,%3}, [%4];"
                 : "=r"(r0), "=r"(r1), "=r"(r2), "=r"(r3) : "r"(addr));
}
__device__ __forceinline__ void mma16816(float &c0, float &c1, float &c2, float &c3,
                                         uint32_t a0, uint32_t a1, uint32_t a2, uint32_t a3,
                                         uint32_t b0, uint32_t b1) {
    asm volatile("mma.sync.aligned.m16n8k16.row.col.f32.f16.f16.f32 "
                 "{%0,%1,%2,%3}, {%4,%5,%6,%7}, {%8,%9}, {%0,%1,%2,%3};"
                 : "+f"(c0), "+f"(c1), "+f"(c2), "+f"(c3)
                 : "r"(a0), "r"(a1), "r"(a2), "r"(a3), "r"(b0), "r"(b1));
}

// implicit-LinOSS per-p recurrence coefficients
__device__ __forceinline__ void lin_coefs(const float* __restrict__ A_diag,
                                          const float* __restrict__ steps, int p,
                                          float& m11, float& m12, float& m21, float& m22,
                                          float& f1, float& f2) {
    float A  = fmaxf(A_diag[p], 0.0f);
    float dt = 1.0f / (1.0f + expf(-steps[p]));
    float dt2A = dt * dt * A;
    float S  = 1.0f / (1.0f + dt2A);
    m11 = 1.0f - dt2A * S;
    m12 = -dt * A * S;
    m21 = dt * S;
    m22 = S;
    f1  = m11 * dt;
    f2  = m21 * dt;
}

// ================= kernel A: build fused matrices + power tables (81 blocks) =================
// blocks 0-31 : BW rows (8 per block)      blocks 32-63: Wc rows (10 per block)
// blocks 64-79: power table (8 j per block, binary exponentiation)
__global__ __launch_bounds__(256) void kA(const float* __restrict__ W_in,
                                          const float* __restrict__ b_in,
                                          const float* __restrict__ A_diag,
                                          const float* __restrict__ Bmat,
                                          const float* __restrict__ Cmat,
                                          const float* __restrict__ Dvec,
                                          const float* __restrict__ steps,
                                          const float* __restrict__ W_out,
                                          const float* __restrict__ b_out) {
    __shared__ float sbuf[9600];
    const int bid = blockIdx.x, tid = threadIdx.x;

    if (bid < 32) {
        // BW[k][i] = sum_h B_part[k][h] * W_in[h][i]; 8 k-rows per block
        float* Wins = sbuf;                   // [128*64] flat
        float* Bs   = sbuf + DMODEL * INDIM;  // [8][128]
        {
            const float4* src = (const float4*)W_in;
            float4* dst = (float4*)Wins;
            #pragma unroll
            for (int it = 0; it < 8; it++) dst[tid + it * 256] = src[tid + it * 256];
        }
        const int k0 = bid * 8;
        for (int i = tid; i < 8 * DMODEL; i += 256) {
            int kk = i >> 7, h = i & 127;
            int k = k0 + kk, p = k & 127, part = k >> 7;
            Bs[i] = Bmat[(p * DMODEL + h) * 2 + part];
        }
        __syncthreads();
        #pragma unroll
        for (int e = tid; e < 8 * INDIM; e += 256) {
            int kk = e >> 6, i = e & 63;
            float a0 = 0.0f, a1 = 0.0f;
            #pragma unroll 8
            for (int h = 0; h < DMODEL; h += 2) {
                a0 = fmaf(Bs[kk * DMODEL + h],     Wins[h * INDIM + i],       a0);
                a1 = fmaf(Bs[kk * DMODEL + h + 1], Wins[(h + 1) * INDIM + i], a1);
            }
            g_BWh[(k0 + kk) * INDIM + i] = __float2half(a0 + a1);
        }
        if (bid == 0) {
            int k = tid, p = k & 127, part = k >> 7;
            float s = 0.0f;
            for (int h = 0; h < DMODEL; h++) s = fmaf(Bmat[(p * DMODEL + h) * 2 + part], b_in[h], s);
            g_BuC[k] = s;
        }
    } else if (bid < 64) {
        // Wc rows: k<128: W_out*C_re ; k<256: -W_out*C_im ; else W_out*diag(D)*W_in
        float* Wos = sbuf;                    // [64][129] padded (8256)
        float* Cs  = sbuf + OUTDIM * 129;     // [10][128]  (1280)
        {
            const float4* src = (const float4*)W_out;
            #pragma unroll
            for (int it = 0; it < 8; it++) {
                int idx = tid + it * 256;           // float4 index over 64x128
                int o = idx >> 5, h0 = (idx & 31) * 4;
                float4 v = src[idx];
                float* d = Wos + o * 129 + h0;
                d[0] = v.x; d[1] = v.y; d[2] = v.z; d[3] = v.w;
            }
        }
        const int kb0 = (bid - 32) * 10;
        for (int i = tid; i < 10 * DMODEL; i += 256) {
            int kk = i >> 7, h = i & 127;
            int k = kb0 + kk;
            float v;
            if (k < 128)      v =  Cmat[(h * DMODEL + k) * 2 + 0];
            else if (k < 256) v = -Cmat[(h * DMODEL + (k - 128)) * 2 + 1];
            else              v =  Dvec[h] * W_in[h * INDIM + (k - 256)];
            Cs[i] = v;
        }
        __syncthreads();
        for (int e = tid; e < 10 * OUTDIM; e += 256) {
            int kk = e >> 6, o = e & 63;
            float a0 = 0.0f, a1 = 0.0f;
            #pragma unroll 8
            for (int h = 0; h < DMODEL; h += 2) {
                a0 = fmaf(Cs[kk * DMODEL + h],     Wos[o * 129 + h],     a0);
                a1 = fmaf(Cs[kk * DMODEL + h + 1], Wos[o * 129 + h + 1], a1);
            }
            g_WcF[o * 320 + (kb0 + kk)] = __float2half(a0 + a1);
        }
        if (bid == 32 && tid < OUTDIM) {
            float s = b_out[tid];
            for (int h = 0; h < DMODEL; h++) s = fmaf(W_out[tid * DMODEL + h] * Dvec[h], b_in[h], s);
            g_bias[tid] = s;
        }
    } else {
        // power table: block covers 8 j values; thread (p, jh) does 4 of them.
        const int p  = tid & 127;
        const int jh = tid >> 7;                   // 0 or 1
        const int jbase = (bid - 64) * 8 + jh * 4;
        float m11, m12, m21, m22, f1, f2;
        lin_coefs(A_diag, steps, p, m11, m12, m21, m22, f1, f2);
        #pragma unroll
        for (int u = 0; u < 4; u++) {
            const int j = jbase + u;
            // compute M^(j+1) by binary exponentiation (powers commute)
            unsigned e = (unsigned)(j + 1);
            float r11 = 1.f, r12 = 0.f, r21 = 0.f, r22 = 1.f;
            float p11 = m11, p12 = m12, p21 = m21, p22 = m22;
            while (e) {
                if (e & 1u) {
                    float n11 = r11 * p11 + r12 * p21;
                    float n12 = r11 * p12 + r12 * p22;
                    float n21 = r21 * p11 + r22 * p21;
                    float n22 = r21 * p12 + r22 * p22;
                    r11 = n11; r12 = n12; r21 = n21; r22 = n22;
                }
                e >>= 1;
                if (e) {
                    float q11 = p11 * p11 + p12 * p21;
                    float q12 = p11 * p12 + p12 * p22;
                    float q21 = p21 * p11 + p22 * p21;
                    float q22 = p21 * p12 + p22 * p22;
                    p11 = q11; p12 = q12; p21 = q21; p22 = q22;
                }
            }
            g_Pm[j * DMODEL + p]  = make_float4(r11, r12, r21, r22);
            g_Pzw[j * DMODEL + p] = make_float2(r21, r22);
        }
    }
}

// ================= kernel B: tensor-core Bu GEMM + fused chunk-local scan (R10 form) =================
// Dynamic smem: xh [128][72] f16 | BWh [256][72] f16 | Bus [128][264] f32
#define KB_XH    0
#define KB_BWH   18432
#define KB_BUS   55296
#define KB_SMEM  190464
#define APAD 72
#define BUSP 264
__global__ __launch_bounds__(256) void kB(const float* __restrict__ x,
                                          const float* __restrict__ A_diag,
                                          const float* __restrict__ steps) {
    extern __shared__ char dsm[];
    __half* xh  = (__half*)(dsm + KB_XH);
    __half* bwh = (__half*)(dsm + KB_BWH);
    float*  bus = (float*)(dsm + KB_BUS);

    const int b = blockIdx.x >> 5, c = blockIdx.x & 31;
    const int R0 = b * LSEQ + c * TCHUNK;
    const int tid = threadIdx.x;
    const int wid = tid >> 5, lane = tid & 31;

    // ---- stage x tile -> fp16 [128][72] ----
    {
        const float4* xg = (const float4*)(x + (size_t)R0 * INDIM);
        #pragma unroll
        for (int it = 0; it < 8; it++) {
            int idx = tid + it * 256;            // float4 index, 2048 total
            int r = idx >> 4, c4 = idx & 15;
            float4 v = xg[idx];
            __half2 h0 = __floats2half2_rn(v.x, v.y);
            __half2 h1 = __floats2half2_rn(v.z, v.w);
            *(uint2*)(xh + r * APAD + c4 * 4) =
                make_uint2(*(uint32_t*)&h0, *(uint32_t*)&h1);
        }
    }
    // ---- stage BW -> [256][72] ----
    {
        const uint4* bg = (const uint4*)g_BWh;   // 8 halves per uint4, 2048 total
        #pragma unroll
        for (int it = 0; it < 8; it++) {
            int idx = tid + it * 256;
            int r = idx >> 3, seg = idx & 7;
            *(uint4*)(bwh + r * APAD + seg * 8) = bg[idx];
        }
    }
    __syncthreads();

    // ---- GEMM1: warp wid computes rows 16*wid..+15, cols 0..255 ----
    {
        const uint32_t sX = smem_u32(xh), sW = smem_u32(bwh);
        const int q = lane >> 3, rr = lane & 7;
        const uint32_t aBase = sX + (uint32_t)(((wid * 16 + (q & 1) * 8 + rr) * APAD + (q >> 1) * 8) * 2);
        const uint32_t bBase0 = sW + (uint32_t)((((q >> 1) * 8 + rr) * APAD + (q & 1) * 8) * 2);

        float acc[32][4];
        #pragma unroll
        for (int nt = 0; nt < 32; nt++) {
            acc[nt][0] = 0.f; acc[nt][1] = 0.f; acc[nt][2] = 0.f; acc[nt][3] = 0.f;
        }
        #pragma unroll
        for (int k16 = 0; k16 < 4; k16++) {
            uint32_t a0, a1, a2, a3;
            ldsm_x4(a0, a1, a2, a3, aBase + (uint32_t)(k16 * 32));
            #pragma unroll
            for (int ntp = 0; ntp < 16; ntp++) {
                uint32_t b0, b1, b2, b3;
                ldsm_x4(b0, b1, b2, b3, bBase0 + (uint32_t)(ntp * 16 * APAD * 2 + k16 * 32));
                mma16816(acc[ntp * 2][0], acc[ntp * 2][1], acc[ntp * 2][2], acc[ntp * 2][3],
                         a0, a1, a2, a3, b0, b1);
                mma16816(acc[ntp * 2 + 1][0], acc[ntp * 2 + 1][1], acc[ntp * 2 + 1][2], acc[ntp * 2 + 1][3],
                         a0, a1, a2, a3, b2, b3);
            }
        }
        // fragments -> Bus
        const int g = lane >> 2, ci = lane & 3;
        const int row0 = wid * 16 + g;
        #pragma unroll
        for (int nt = 0; nt < 32; nt++) {
            int col = nt * 8 + ci * 2;
            *(float2*)(bus + row0 * BUSP + col)       = make_float2(acc[nt][0], acc[nt][1]);
            *(float2*)(bus + (row0 + 8) * BUSP + col) = make_float2(acc[nt][2], acc[nt][3]);
        }
    }
    __syncthreads();

    // ---- fused chunk-local scan: thread k over 128 t, fp16 w stores ----
    {
        const int k = tid, p = k & 127;
        float m11, m12, m21, m22, f1, f2;
        lin_coefs(A_diag, steps, p, m11, m12, m21, m22, f1, f2);
        const float buc = g_BuC[k];
        float z = 0.0f, w = 0.0f;
        __half* wout = g_w + (size_t)R0 * CHAINS + k;
        const float* bcol = bus + k;
        for (int t = 0; t < TCHUNK; t += 4) {
            float bu[4];
            #pragma unroll
            for (int j = 0; j < 4; j++) bu[j] = bcol[(t + j) * BUSP] + buc;
            #pragma unroll
            for (int j = 0; j < 4; j++) {
                float nz = fmaf(m11, z, fmaf(m12, w, f1 * bu[j]));
                float nw = fmaf(m21, z, fmaf(m22, w, f2 * bu[j]));
                z = nz; w = nw;
                wout[(size_t)(t + j) * CHAINS] = __float2half(w);
            }
        }
        g_carry[(b * NCHUNK + c) * CHAINS + k] = make_float2(z, w);
    }
}

// ================= kernel C: cross-chunk scan of carries (prefetched) =================
__global__ __launch_bounds__(256) void kC() {
    const int b = blockIdx.x, k = threadIdx.x, p = k & 127;
    const float4 mt = g_Pm[(TCHUNK - 1) * DMODEL + p];   // M^TCHUNK
    float z = 0.0f, w = 0.0f;
    for (int c0 = 0; c0 < NCHUNK; c0 += 8) {
        float2 lc[8];
        #pragma unroll
        for (int j = 0; j < 8; j++)
            lc[j] = g_carry[(b * NCHUNK + c0 + j) * CHAINS + k];
        #pragma unroll
        for (int j = 0; j < 8; j++) {
            g_cin[(b * NCHUNK + c0 + j) * CHAINS + k] = make_float2(z, w);
            float nz = fmaf(mt.x, z, fmaf(mt.y, w, lc[j].x));
            float nw = fmaf(mt.z, z, fmaf(mt.w, w, lc[j].y));
            z = nz; w = nw;
        }
    }
}

// ================= kernel D: carry fixup + output GEMM via mma.sync f16 (R10 form) =================
__global__ __launch_bounds__(256) void kD(const float* __restrict__ x,
                                          float* __restrict__ out) {
    __shared__ __half smA[128 * APAD];   // 18KB
    __shared__ __half smB[64 * APAD];    // 9KB
    __shared__ float czs[CHAINS], cws[CHAINS];

    const int R0 = blockIdx.x * 128;          // global row = b*LSEQ + t0
    const int b  = R0 >> 12;
    const int cc = (R0 & 4095) >> 7;          // chunk index
    const int tid = threadIdx.x;
    const int wid = tid >> 5, lane = tid & 31;

    {
        float2 ci = g_cin[(b * NCHUNK + cc) * CHAINS + tid];
        czs[tid] = ci.x; cws[tid] = ci.y;
    }

    const uint32_t sA = smem_u32(smA);
    const uint32_t sB = smem_u32(smB);

    const int q  = lane >> 3, rr = lane & 7;
    const uint32_t aBase = sA + (uint32_t)(((wid * 16 + (q & 1) * 8 + rr) * APAD + (q >> 1) * 8) * 2);
    uint32_t bBase[4];
    #pragma unroll
    for (int ntp = 0; ntp < 4; ntp++)
        bBase[ntp] = sB + (uint32_t)(((ntp * 16 + (q >> 1) * 8 + rr) * APAD + (q & 1) * 8) * 2);

    const int kp = lane;            // k-pair within slice (k = 2kp, 2kp+1)
    const int rq = wid;             // 16-row segment
    const int brow = tid >> 2, bseg = tid & 3;   // B: row o, 16-half segment

    float acc[8][4];
    #pragma unroll
    for (int nt = 0; nt < 8; nt++)
        #pragma unroll
        for (int i = 0; i < 4; i++) acc[nt][i] = 0.0f;

    for (int s = 0; s < 5; s++) {
        __syncthreads();
        // ---- stage B slice: 64 o-rows x 64 k halves ----
        {
            const uint4* src = (const uint4*)(g_WcF + brow * 320 + s * 64 + bseg * 16);
            uint4 v0 = src[0], v1 = src[1];
            uint4* dst = (uint4*)(smB + brow * APAD + bseg * 16);
            dst[0] = v0; dst[1] = v1;
        }
        // ---- stage A slice: 128 rows x 64 k, fp16 w load + fp32 fixup + cvt fp16 ----
        if (s < 4) {
            const int k2 = kp * 2;
            const int kg = s * 64 + k2;
            const int p0 = kg & 127;
            const float cz0 = czs[kg],     cw0 = cws[kg];
            const float cz1 = czs[kg + 1], cw1 = cws[kg + 1];
            const __half* wsrc = g_w + (size_t)R0 * CHAINS + kg;
            #pragma unroll 4
            for (int j = 0; j < 16; j++) {
                int r = rq * 16 + j;
                float4 pz = *(const float4*)(&g_Pzw[r * DMODEL + p0]);  // {z0,w0,z1,w1}
                __half2 wh = *(const __half2*)(wsrc + (size_t)r * CHAINS);
                float2 wf = __half22float2(wh);
                float v0 = fmaf(pz.x, cz0, fmaf(pz.y, cw0, wf.x));
                float v1 = fmaf(pz.z, cz1, fmaf(pz.w, cw1, wf.y));
                *(__half2*)(smA + r * APAD + k2) = __floats2half2_rn(v0, v1);
            }
        } else {
            const int k2 = kp * 2;
            const float* xsrc = x + (size_t)R0 * INDIM + k2;
            #pragma unroll 4
            for (int j = 0; j < 16; j++) {
                int r = rq * 16 + j;
                float2 xv = *(const float2*)(xsrc + (size_t)r * INDIM);
                *(__half2*)(smA + r * APAD + k2) = __floats2half2_rn(xv.x, xv.y);
            }
        }
        __syncthreads();

        // ---- compute: 4 k16 steps ----
        #pragma unroll
        for (int k16 = 0; k16 < 4; k16++) {
            const uint32_t kofs = (uint32_t)(k16 * 16 * 2);
            uint32_t a0, a1, a2, a3;
            ldsm_x4(a0, a1, a2, a3, aBase + kofs);
            uint32_t bf[4][4];
            #pragma unroll
            for (int ntp = 0; ntp < 4; ntp++)
                ldsm_x4(bf[ntp][0], bf[ntp][1], bf[ntp][2], bf[ntp][3], bBase[ntp] + kofs);
            #pragma unroll
            for (int ntp = 0; ntp < 4; ntp++) {
                mma16816(acc[ntp * 2][0], acc[ntp * 2][1], acc[ntp * 2][2], acc[ntp * 2][3],
                         a0, a1, a2, a3, bf[ntp][0], bf[ntp][1]);
                mma16816(acc[ntp * 2 + 1][0], acc[ntp * 2 + 1][1], acc[ntp * 2 + 1][2], acc[ntp * 2 + 1][3],
                         a0, a1, a2, a3, bf[ntp][2], bf[ntp][3]);
            }
        }
    }

    // ---- epilogue: add bias, store directly from fragments ----
    const int g = lane >> 2, cpair = (lane & 3) * 2;
    const int row0 = R0 + wid * 16 + g;
    float* og0 = out + (size_t)row0 * OUTDIM;
    float* og1 = og0 + 8 * OUTDIM;
    #pragma unroll
    for (int nt = 0; nt < 8; nt++) {
        int col = nt * 8 + cpair;
        float b0 = g_bias[col], b1 = g_bias[col + 1];
        *(float2*)(og0 + col) = make_float2(acc[nt][0] + b0, acc[nt][1] + b1);
        *(float2*)(og1 + col) = make_float2(acc[nt][2] + b0, acc[nt][3] + b1);
    }
}

extern "C" void kernel_launch(void* const* d_in, const int* in_sizes, int n_in,
                              void* d_out, int out_size) {
    const float* x      = (const float*)d_in[0];
    const float* W_in   = (const float*)d_in[1];
    const float* b_in   = (const float*)d_in[2];
    const float* A_diag = (const float*)d_in[3];
    const float* Bmat   = (const float*)d_in[4];
    const float* Cmat   = (const float*)d_in[5];
    const float* Dvec   = (const float*)d_in[6];
    const float* steps  = (const float*)d_in[7];
    const float* W_out  = (const float*)d_in[8];
    const float* b_out  = (const float*)d_in[9];
    float* out = (float*)d_out;

    cudaFuncSetAttribute(kB, cudaFuncAttributeMaxDynamicSharedMemorySize, KB_SMEM);

    kA<<<80, 256>>>(W_in, b_in, A_diag, Bmat, Cmat, Dvec, steps, W_out, b_out);
    kB<<<BATCH * NCHUNK, 256, KB_SMEM>>>(x, A_diag, steps);
    kC<<<BATCH, 256>>>();
    kD<<<(BATCH * LSEQ) / TCHUNK, 256>>>(x, out);
}